// round 3
// baseline (speedup 1.0000x reference)
#include <cuda_runtime.h>
#include <math.h>

#define LSEQ 1024
#define DMODEL 2048
#define DI 4096
#define NSTATE 16
#define RLOW 128
#define NEXP 8
#define ISZ 5632
#define EPSF 1e-6f

// ---------------- scratch (device globals; no allocation allowed) ----------------
__device__ float g_hsn[LSEQ * DMODEL];          // rmsnorm(hidden)
__device__ float g_xz[LSEQ * 2 * DI];           // in_proj output
__device__ float g_xc[LSEQ * DI];               // conv+silu output
__device__ float g_xdb[LSEQ * 160];             // x_proj output
__device__ float g_dtn[LSEQ * RLOW];            // rmsnorm(dt)
__device__ float g_Bn[LSEQ * NSTATE];
__device__ float g_Cn[LSEQ * NSTATE];
__device__ float g_dt[LSEQ * DI];               // softplus(dt_proj)
__device__ float g_y[LSEQ * DI];                // scan out, gated
__device__ float g_mamba[LSEQ * DMODEL];
__device__ float g_hs2[LSEQ * DMODEL];          // rmsnorm(residual)
__device__ float g_gbuf[2 * LSEQ * ISZ];        // MoE w1 out, then silu(g)*u
__device__ float g_ubuf[2 * LSEQ * ISZ];        // MoE w3 out
__device__ float g_ybuf[2 * LSEQ * DMODEL];     // MoE w2 out (per assignment)
__device__ int   g_cnt[NEXP];
__device__ int   g_off[NEXP];
__device__ int   g_cur[NEXP];
__device__ int   g_tok_e[2 * LSEQ];
__device__ float g_tok_w[2 * LSEQ];
__device__ int   g_assign_tok[2 * LSEQ];
__device__ float g_gate[2 * LSEQ];
__device__ int   g_tok_slot[2 * LSEQ];

// ---------------- small helpers ----------------
__device__ __forceinline__ float siluf(float x) { return x / (1.0f + expf(-x)); }
__device__ __forceinline__ float softplusf(float x) {
    return (x > 0.0f) ? (x + log1pf(expf(-x))) : log1pf(expf(x));
}

// ---------------- RMSNorm of hidden_states ----------------
__global__ void k_rms1(const float* __restrict__ x, const float* __restrict__ w,
                       float* __restrict__ out) {
    int row = blockIdx.x, t = threadIdx.x;
    __shared__ float red[256];
    float s = 0.0f;
    for (int i = t; i < DMODEL; i += 256) { float v = x[row * DMODEL + i]; s += v * v; }
    red[t] = s; __syncthreads();
    for (int st = 128; st > 0; st >>= 1) { if (t < st) red[t] += red[t + st]; __syncthreads(); }
    float inv = rsqrtf(red[0] / (float)DMODEL + EPSF);
    for (int i = t; i < DMODEL; i += 256)
        out[row * DMODEL + i] = x[row * DMODEL + i] * inv * w[i];
}

// ==== 128x128x8 NT-SGEMM core (A[M,K] row-major, B[N,K] row-major, C=A*B^T) ====
// 256 threads, 8x8 micro-tile. Optional row-gather for A (toks != nullptr).
__device__ __forceinline__ void gemm_nt_body(
    const float* __restrict__ A, const float* __restrict__ B, float* __restrict__ C,
    int M, int N, int K, int bm, int bn, const int* toks /*smem, 128 entries or null*/,
    size_t c_row_stride) {
    __shared__ float As[8][128];
    __shared__ float Bs[8][128];
    int t = threadIdx.x;
    int lr = t >> 1;             // load row 0..127
    int lk = (t & 1) * 4;        // k sub-offset 0 or 4
    int tx = t & 15, ty = t >> 4;
    float acc[8][8] = {};
    int arow;
    if (toks) arow = toks[lr];                    // gathered row (-1 = pad)
    else      arow = (bm + lr < M) ? (bm + lr) : -1;
    bool bok = (bn + lr < N);
    const float* Aptr = (arow >= 0) ? &A[(size_t)arow * K] : A;
    const float* Bptr = bok ? &B[(size_t)(bn + lr) * K] : B;

    for (int k0 = 0; k0 < K; k0 += 8) {
        float4 av = make_float4(0.f, 0.f, 0.f, 0.f);
        float4 bv = make_float4(0.f, 0.f, 0.f, 0.f);
        if (arow >= 0) av = *(const float4*)&Aptr[k0 + lk];
        if (bok)       bv = *(const float4*)&Bptr[k0 + lk];
        As[lk + 0][lr] = av.x; As[lk + 1][lr] = av.y; As[lk + 2][lr] = av.z; As[lk + 3][lr] = av.w;
        Bs[lk + 0][lr] = bv.x; Bs[lk + 1][lr] = bv.y; Bs[lk + 2][lr] = bv.z; Bs[lk + 3][lr] = bv.w;
        __syncthreads();
#pragma unroll
        for (int k = 0; k < 8; k++) {
            float ar[8], br[8];
            *(float4*)&ar[0] = *(float4*)&As[k][ty * 8];
            *(float4*)&ar[4] = *(float4*)&As[k][ty * 8 + 4];
            *(float4*)&br[0] = *(float4*)&Bs[k][tx * 8];
            *(float4*)&br[4] = *(float4*)&Bs[k][tx * 8 + 4];
#pragma unroll
            for (int i = 0; i < 8; i++)
#pragma unroll
                for (int j = 0; j < 8; j++)
                    acc[i][j] += ar[i] * br[j];
        }
        __syncthreads();
    }
#pragma unroll
    for (int i = 0; i < 8; i++) {
        int r = bm + ty * 8 + i;
        if (r < M) {
#pragma unroll
            for (int j = 0; j < 8; j++) {
                int c = bn + tx * 8 + j;
                if (c < N) C[(size_t)r * c_row_stride + c] = acc[i][j];
            }
        }
    }
}

__global__ __launch_bounds__(256) void k_gemm_nt(
    const float* __restrict__ A, const float* __restrict__ B, float* __restrict__ C,
    int M, int N, int K) {
    gemm_nt_body(A, B, C, M, N, K, blockIdx.y * 128, blockIdx.x * 128, nullptr, (size_t)N);
}

// ---------------- causal depthwise conv (K=4) + bias + silu ----------------
__global__ void k_conv(const float* __restrict__ cw, const float* __restrict__ cb) {
    int idx = blockIdx.x * 256 + threadIdx.x;
    if (idx >= LSEQ * DI) return;
    int c = idx % DI, l = idx / DI;
    float s = cb[c];
#pragma unroll
    for (int k = 0; k < 4; k++) {
        int ll = l - 3 + k;
        if (ll >= 0) s += g_xz[(size_t)ll * 2 * DI + c] * cw[c * 4 + k];
    }
    g_xc[idx] = siluf(s);
}

// ---------------- rmsnorm of dt / B / C slices of xdb ----------------
__global__ void k_norm3(const float* __restrict__ wdt, const float* __restrict__ wb,
                        const float* __restrict__ wc) {
    int row = blockIdx.x, i = threadIdx.x;   // 128 threads
    __shared__ float sdt[128];
    __shared__ float sb[16], sc[16];
    float v = g_xdb[row * 160 + i];
    sdt[i] = v * v;
    float bv = 0.f, cv = 0.f;
    if (i < 16) {
        bv = g_xdb[row * 160 + 128 + i];
        cv = g_xdb[row * 160 + 144 + i];
        sb[i] = bv * bv; sc[i] = cv * cv;
    }
    __syncthreads();
    for (int st = 64; st > 0; st >>= 1) { if (i < st) sdt[i] += sdt[i + st]; __syncthreads(); }
    for (int st = 8; st > 0; st >>= 1) { if (i < st) { sb[i] += sb[i + st]; sc[i] += sc[i + st]; } __syncthreads(); }
    float invdt = rsqrtf(sdt[0] / (float)RLOW + EPSF);
    g_dtn[row * RLOW + i] = v * invdt * wdt[i];
    if (i < 16) {
        g_Bn[row * NSTATE + i] = bv * rsqrtf(sb[0] / (float)NSTATE + EPSF) * wb[i];
        g_Cn[row * NSTATE + i] = cv * rsqrtf(sc[0] / (float)NSTATE + EPSF) * wc[i];
    }
}

// ---------------- dt bias + softplus (in place) ----------------
__global__ void k_dtact(const float* __restrict__ b) {
    int idx = blockIdx.x * 256 + threadIdx.x;
    if (idx >= LSEQ * DI) return;
    int c = idx % DI;
    g_dt[idx] = softplusf(g_dt[idx] + b[c]);
}

// ---------------- selective scan: one lane per (d, n), shfl-reduce over n ----
__global__ __launch_bounds__(256) void k_scan(const float* __restrict__ A_log,
                                              const float* __restrict__ Dp) {
    int tid = blockIdx.x * 256 + threadIdx.x;
    int lane = tid & 31;
    int warp = tid >> 5;
    int n = lane & 15;
    int d = warp * 2 + (lane >> 4);
    if (d >= DI) return;
    float Acoef = -expf(A_log[d * NSTATE + n]);
    float Dcoef = Dp[d];
    float h = 0.0f;
    for (int l = 0; l < LSEQ; l++) {
        float dtv = g_dt[(size_t)l * DI + d];
        float xv  = g_xc[(size_t)l * DI + d];
        float bvv = g_Bn[l * NSTATE + n];
        float cvv = g_Cn[l * NSTATE + n];
        float dA = expf(dtv * Acoef);
        h = h * dA + dtv * xv * bvv;
        float y = h * cvv;
        y += __shfl_xor_sync(0xffffffffu, y, 8);
        y += __shfl_xor_sync(0xffffffffu, y, 4);
        y += __shfl_xor_sync(0xffffffffu, y, 2);
        y += __shfl_xor_sync(0xffffffffu, y, 1);
        if (n == 0) {
            float zv = g_xz[(size_t)l * 2 * DI + DI + d];
            g_y[(size_t)l * DI + d] = (y + xv * Dcoef) * siluf(zv);
        }
    }
}

// ---------------- residual add + rmsnorm ----------------
__global__ void k_addrms(const float* __restrict__ hid, const float* __restrict__ w,
                         float* __restrict__ resid_out) {
    int row = blockIdx.x, t = threadIdx.x;
    __shared__ float red[256];
    float s = 0.0f;
    for (int i = t; i < DMODEL; i += 256) {
        float r = g_mamba[row * DMODEL + i] + hid[row * DMODEL + i];
        resid_out[row * DMODEL + i] = r;
        s += r * r;
    }
    red[t] = s; __syncthreads();
    for (int st = 128; st > 0; st >>= 1) { if (t < st) red[t] += red[t + st]; __syncthreads(); }
    float inv = rsqrtf(red[0] / (float)DMODEL + EPSF);
    for (int i = t; i < DMODEL; i += 256)
        g_hs2[row * DMODEL + i] = resid_out[row * DMODEL + i] * inv * w[i];
}

// ---------------- router: logits, softmax, top2, counts ----------------
__global__ void k_zero_router() {
    int t = threadIdx.x;
    if (t < NEXP) { g_cnt[t] = 0; g_cur[t] = 0; }
}

__global__ void k_router(const float* __restrict__ rw) {
    int trow = blockIdx.x, t = threadIdx.x;
    int w = t >> 5, lane = t & 31;
    __shared__ float lg[NEXP];
    float s = 0.0f;
    for (int i = lane; i < DMODEL; i += 32) s += g_hs2[trow * DMODEL + i] * rw[w * DMODEL + i];
    for (int o = 16; o > 0; o >>= 1) s += __shfl_xor_sync(0xffffffffu, s, o);
    if (lane == 0) lg[w] = s;
    __syncthreads();
    if (t == 0) {
        float mx = lg[0];
        for (int e = 1; e < NEXP; e++) mx = fmaxf(mx, lg[e]);
        float ex[NEXP], sum = 0.0f;
        for (int e = 0; e < NEXP; e++) { ex[e] = expf(lg[e] - mx); sum += ex[e]; }
        int e0 = 0;
        for (int e = 1; e < NEXP; e++) if (ex[e] > ex[e0]) e0 = e;
        int e1 = -1;
        for (int e = 0; e < NEXP; e++) if (e != e0 && (e1 < 0 || ex[e] > ex[e1])) e1 = e;
        g_tok_e[2 * trow] = e0; g_tok_e[2 * trow + 1] = e1;
        g_tok_w[2 * trow] = ex[e0] / sum; g_tok_w[2 * trow + 1] = ex[e1] / sum;
        atomicAdd(&g_cnt[e0], 1); atomicAdd(&g_cnt[e1], 1);
    }
}

__global__ void k_offsets() {
    int o = 0;
    for (int e = 0; e < NEXP; e++) { g_off[e] = o; o += g_cnt[e]; }
}

__global__ void k_assign() {
    int t = blockIdx.x * 256 + threadIdx.x;
    if (t >= LSEQ) return;
    for (int j = 0; j < 2; j++) {
        int e = g_tok_e[2 * t + j];
        int p = atomicAdd(&g_cur[e], 1);
        int slot = g_off[e] + p;
        g_assign_tok[slot] = t;
        g_gate[slot] = g_tok_w[2 * t + j];
        g_tok_slot[2 * t + j] = slot;
    }
}

// ---------------- MoE up-projection (gathered rows), out[slot, I] ----------------
__global__ __launch_bounds__(256) void k_moe_up(const float* __restrict__ W,
                                                float* __restrict__ Obuf) {
    int e = blockIdx.z;
    int cnt = g_cnt[e], off = g_off[e];
    int bm = blockIdx.y * 128;
    if (bm >= cnt) return;
    __shared__ int toks[128];
    int t = threadIdx.x;
    if (t < 128) toks[t] = (bm + t < cnt) ? g_assign_tok[off + bm + t] : -1;
    __syncthreads();
    gemm_nt_body(g_hs2, W + (size_t)e * ISZ * DMODEL, Obuf + (size_t)off * ISZ,
                 cnt, ISZ, DMODEL, bm, blockIdx.x * 128, toks, (size_t)ISZ);
}

// ---------------- h = silu(g) * u (in place into gbuf) ----------------
__global__ void k_moe_h() {
    int idx = blockIdx.x * 256 + threadIdx.x;
    if (idx >= 2 * LSEQ * ISZ) return;
    float g = g_gbuf[idx];
    g_gbuf[idx] = siluf(g) * g_ubuf[idx];
}

// ---------------- MoE down-projection: ybuf[slot, D] = h @ w2[e]^T ----------------
__global__ __launch_bounds__(256) void k_moe_down(const float* __restrict__ W2) {
    int e = blockIdx.z;
    int cnt = g_cnt[e], off = g_off[e];
    int bm = blockIdx.y * 128;
    if (bm >= cnt) return;
    gemm_nt_body(g_gbuf + (size_t)off * ISZ, W2 + (size_t)e * DMODEL * ISZ,
                 g_ybuf + (size_t)off * DMODEL,
                 cnt, DMODEL, ISZ, bm, blockIdx.x * 128, nullptr, (size_t)DMODEL);
}

// ---------------- combine two experts per token ----------------
__global__ void k_combine(float* __restrict__ moe_out) {
    int idx = blockIdx.x * 256 + threadIdx.x;
    if (idx >= LSEQ * DMODEL) return;
    int t = idx / DMODEL, d = idx % DMODEL;
    int s0 = g_tok_slot[2 * t], s1 = g_tok_slot[2 * t + 1];
    moe_out[idx] = g_gate[s0] * g_ybuf[(size_t)s0 * DMODEL + d] +
                   g_gate[s1] * g_ybuf[(size_t)s1 * DMODEL + d];
}

// =======================================================================

extern "C" void kernel_launch(void* const* d_in, const int* in_sizes, int n_in,
                              void* d_out, int out_size) {
    (void)in_sizes; (void)n_in;
    const float* hidden    = (const float*)d_in[0];
    const float* ln_in_w   = (const float*)d_in[1];
    const float* in_proj_w = (const float*)d_in[2];
    const float* conv_w    = (const float*)d_in[3];
    const float* conv_b    = (const float*)d_in[4];
    const float* x_proj_w  = (const float*)d_in[5];
    const float* dt_ln_w   = (const float*)d_in[6];
    const float* b_ln_w    = (const float*)d_in[7];
    const float* c_ln_w    = (const float*)d_in[8];
    const float* dt_proj_w = (const float*)d_in[9];
    const float* dt_proj_b = (const float*)d_in[10];
    const float* A_log     = (const float*)d_in[11];
    const float* D_param   = (const float*)d_in[12];
    const float* out_proj_w= (const float*)d_in[13];
    const float* ln_ff_w   = (const float*)d_in[14];
    const float* router_w  = (const float*)d_in[15];
    const float* w1        = (const float*)d_in[16];
    const float* w3        = (const float*)d_in[17];
    const float* w2        = (const float*)d_in[18];
    float* out = (float*)d_out;
    float* moe_out   = out;                          // [1024,2048]
    float* resid_out = out + (size_t)LSEQ * DMODEL;  // [1024,2048]
    (void)out_size;

    float *p_hsn, *p_xz, *p_xc, *p_xdb, *p_dtn, *p_dt, *p_y, *p_mamba;
    cudaGetSymbolAddress((void**)&p_hsn, g_hsn);
    cudaGetSymbolAddress((void**)&p_xz, g_xz);
    cudaGetSymbolAddress((void**)&p_xc, g_xc);
    cudaGetSymbolAddress((void**)&p_xdb, g_xdb);
    cudaGetSymbolAddress((void**)&p_dtn, g_dtn);
    cudaGetSymbolAddress((void**)&p_dt, g_dt);
    cudaGetSymbolAddress((void**)&p_y, g_y);
    cudaGetSymbolAddress((void**)&p_mamba, g_mamba);

    // 1. rmsnorm(hidden)
    k_rms1<<<LSEQ, 256>>>(hidden, ln_in_w, p_hsn);
    // 2. in_proj: [1024,8192] = hsn @ in_proj_w^T
    k_gemm_nt<<<dim3(8192 / 128, LSEQ / 128), 256>>>(p_hsn, in_proj_w, p_xz, LSEQ, 2 * DI, DMODEL);
    // 3. causal conv + silu
    k_conv<<<(LSEQ * DI) / 256, 256>>>(conv_w, conv_b);
    // 4. x_proj: [1024,160] = xc @ x_proj_w^T
    k_gemm_nt<<<dim3(2, LSEQ / 128), 256>>>(p_xc, x_proj_w, p_xdb, LSEQ, 160, DI);
    // 5. rmsnorms of dt/B/C
    k_norm3<<<LSEQ, 128>>>(dt_ln_w, b_ln_w, c_ln_w);
    // 6. dt_proj + bias + softplus
    k_gemm_nt<<<dim3(DI / 128, LSEQ / 128), 256>>>(p_dtn, dt_proj_w, p_dt, LSEQ, DI, RLOW);
    k_dtact<<<(LSEQ * DI) / 256, 256>>>(dt_proj_b);
    // 7. selective scan (+ D skip + silu(z) gate)
    k_scan<<<(DI * NSTATE) / 256, 256>>>(A_log, D_param);
    // 8. out_proj
    k_gemm_nt<<<dim3(DMODEL / 128, LSEQ / 128), 256>>>(p_y, out_proj_w, p_mamba, LSEQ, DMODEL, DI);
    // 9. residual add + rmsnorm  (residual written straight to d_out)
    k_addrms<<<LSEQ, 256>>>(hidden, ln_ff_w, resid_out);
    // 10. router + expert grouping
    k_zero_router<<<1, 32>>>();
    k_router<<<LSEQ, 256>>>(router_w);
    k_offsets<<<1, 1>>>();
    k_assign<<<LSEQ / 256, 256>>>();
    // 11. MoE up (w1 -> gbuf, w3 -> ubuf)
    float *p_gbuf, *p_ubuf;
    cudaGetSymbolAddress((void**)&p_gbuf, g_gbuf);
    cudaGetSymbolAddress((void**)&p_ubuf, g_ubuf);
    {
        dim3 gup(ISZ / 128, (2 * LSEQ) / 128, NEXP);   // 44 x 16 x 8
        k_moe_up<<<gup, 256>>>(w1, p_gbuf);
        k_moe_up<<<gup, 256>>>(w3, p_ubuf);
    }
    // 12. h = silu(g)*u
    k_moe_h<<<(2 * LSEQ * ISZ) / 256, 256>>>();
    // 13. MoE down
    k_moe_down<<<dim3(DMODEL / 128, (2 * LSEQ) / 128, NEXP), 256>>>(w2);
    // 14. combine with gates -> moe_out
    k_combine<<<(LSEQ * DMODEL) / 256, 256>>>(moe_out);
}

// round 6
// speedup vs baseline: 2.3786x; 2.3786x over previous
#include <cuda_runtime.h>
#include <math.h>

#define LSEQ 1024
#define DMODEL 2048
#define DI 4096
#define NSTATE 16
#define RLOW 128
#define NEXP 8
#define ISZ 5632
#define EPSF 1e-6f
#define XPN 160
#define XKS 8

// ---------------- scratch (device globals; no allocation allowed) ----------------
__device__ float g_hsn[LSEQ * DMODEL];          // rmsnorm(hidden)
__device__ float g_xz[LSEQ * 2 * DI];           // in_proj output
__device__ float g_xc[LSEQ * DI];               // conv+silu output
__device__ float g_xdb[LSEQ * XPN];             // x_proj output
__device__ float g_xdb_part[XKS * LSEQ * XPN];  // split-K partials
__device__ float g_dtn[LSEQ * RLOW];            // rmsnorm(dt)
__device__ float g_Bn[LSEQ * NSTATE];
__device__ float g_Cn[LSEQ * NSTATE];
__device__ float g_dt[LSEQ * DI];               // softplus(dt_proj)
__device__ float g_y[LSEQ * DI];                // scan out, gated
__device__ float g_mamba[LSEQ * DMODEL];
__device__ float g_hs2[LSEQ * DMODEL];          // rmsnorm(residual)
__device__ float g_gbuf[2 * LSEQ * ISZ];        // MoE w1 out, then silu(g)*u
__device__ float g_ubuf[2 * LSEQ * ISZ];        // MoE w3 out
__device__ float g_ybuf[2 * LSEQ * DMODEL];     // MoE w2 out (per assignment)
__device__ int   g_cnt[NEXP];
__device__ int   g_off[NEXP];
__device__ int   g_cur[NEXP];
__device__ int   g_tok_e[2 * LSEQ];
__device__ float g_tok_w[2 * LSEQ];
__device__ int   g_assign_tok[2 * LSEQ];
__device__ float g_gate[2 * LSEQ];
__device__ int   g_tok_slot[2 * LSEQ];

// ---------------- small helpers ----------------
__device__ __forceinline__ float siluf(float x) { return x / (1.0f + expf(-x)); }
__device__ __forceinline__ float softplusf(float x) {
    return (x > 0.0f) ? (x + log1pf(expf(-x))) : log1pf(expf(x));
}
__device__ __forceinline__ unsigned f2tf32(float f) {
    unsigned r; asm("cvt.rna.tf32.f32 %0, %1;" : "=r"(r) : "f"(f)); return r;
}
__device__ __forceinline__ void mma_tf32(float& c0, float& c1, float& c2, float& c3,
    unsigned a0, unsigned a1, unsigned a2, unsigned a3, unsigned b0, unsigned b1) {
    asm("mma.sync.aligned.m16n8k8.row.col.f32.tf32.tf32.f32 "
        "{%0,%1,%2,%3},{%4,%5,%6,%7},{%8,%9},{%0,%1,%2,%3};"
        : "+f"(c0), "+f"(c1), "+f"(c2), "+f"(c3)
        : "r"(a0), "r"(a1), "r"(a2), "r"(a3), "r"(b0), "r"(b1));
}

// ---------------- RMSNorm of hidden_states ----------------
__global__ void k_rms1(const float* __restrict__ x, const float* __restrict__ w,
                       float* __restrict__ out) {
    int row = blockIdx.x, t = threadIdx.x;
    __shared__ float red[256];
    float s = 0.0f;
    for (int i = t; i < DMODEL; i += 256) { float v = x[row * DMODEL + i]; s += v * v; }
    red[t] = s; __syncthreads();
    for (int st = 128; st > 0; st >>= 1) { if (t < st) red[t] += red[t + st]; __syncthreads(); }
    float inv = rsqrtf(red[0] / (float)DMODEL + EPSF);
    for (int i = t; i < DMODEL; i += 256)
        out[row * DMODEL + i] = x[row * DMODEL + i] * inv * w[i];
}

// ==== tf32 tensor-core NT-GEMM: C[M,N] = A[M,K(lda)] * B[N,K(ldb)]^T ====
// 128x128 block tile, BK=16, 256 threads = 8 warps of 64x32.
// Optional A row gather (toks in smem). K range [kbeg,kend).
#define PADT 4
__device__ __forceinline__ void gemm_tf32_body(
    const float* __restrict__ A, const float* __restrict__ B, float* __restrict__ C,
    int M, int N, int bm, int bn, int kbeg, int kend,
    const int* toks, int lda, int ldb, size_t ldc) {
    __shared__ unsigned As[16][128 + PADT];
    __shared__ unsigned Bs[16][128 + PADT];
    int t = threadIdx.x;
    int lane = t & 31, wid = t >> 5;
    int wm = (wid & 1) * 64, wn = (wid >> 1) * 32;
    int g = lane >> 2, q = lane & 3;

    // loader mapping: each thread loads 2 float4 per matrix
    int row0 = t >> 2, row1 = row0 + 64;   // 0..63, 64..127
    int kq = (t & 3) * 4;
    int ar0, ar1;
    if (toks) { ar0 = toks[row0]; ar1 = toks[row1]; }
    else {
        ar0 = (bm + row0 < M) ? bm + row0 : -1;
        ar1 = (bm + row1 < M) ? bm + row1 : -1;
    }
    int br0 = (bn + row0 < N) ? bn + row0 : -1;
    int br1 = (bn + row1 < N) ? bn + row1 : -1;

    float acc[4][4][4];
#pragma unroll
    for (int i = 0; i < 4; i++)
#pragma unroll
        for (int j = 0; j < 4; j++)
#pragma unroll
            for (int r = 0; r < 4; r++) acc[i][j][r] = 0.0f;

    const float4 z4 = make_float4(0.f, 0.f, 0.f, 0.f);
    // prologue: load tile 0
    int kk = kbeg + kq;
    float4 a0v = (ar0 >= 0) ? *(const float4*)&A[(size_t)ar0 * lda + kk] : z4;
    float4 a1v = (ar1 >= 0) ? *(const float4*)&A[(size_t)ar1 * lda + kk] : z4;
    float4 b0v = (br0 >= 0) ? *(const float4*)&B[(size_t)br0 * ldb + kk] : z4;
    float4 b1v = (br1 >= 0) ? *(const float4*)&B[(size_t)br1 * ldb + kk] : z4;
    As[kq + 0][row0] = f2tf32(a0v.x); As[kq + 1][row0] = f2tf32(a0v.y);
    As[kq + 2][row0] = f2tf32(a0v.z); As[kq + 3][row0] = f2tf32(a0v.w);
    As[kq + 0][row1] = f2tf32(a1v.x); As[kq + 1][row1] = f2tf32(a1v.y);
    As[kq + 2][row1] = f2tf32(a1v.z); As[kq + 3][row1] = f2tf32(a1v.w);
    Bs[kq + 0][row0] = f2tf32(b0v.x); Bs[kq + 1][row0] = f2tf32(b0v.y);
    Bs[kq + 2][row0] = f2tf32(b0v.z); Bs[kq + 3][row0] = f2tf32(b0v.w);
    Bs[kq + 0][row1] = f2tf32(b1v.x); Bs[kq + 1][row1] = f2tf32(b1v.y);
    Bs[kq + 2][row1] = f2tf32(b1v.z); Bs[kq + 3][row1] = f2tf32(b1v.w);
    __syncthreads();

    int nk = kend - kbeg;
    for (int k0 = 0; k0 < nk; k0 += 16) {
        bool more = (k0 + 16) < nk;
        if (more) {
            int kn = kbeg + k0 + 16 + kq;
            a0v = (ar0 >= 0) ? *(const float4*)&A[(size_t)ar0 * lda + kn] : z4;
            a1v = (ar1 >= 0) ? *(const float4*)&A[(size_t)ar1 * lda + kn] : z4;
            b0v = (br0 >= 0) ? *(const float4*)&B[(size_t)br0 * ldb + kn] : z4;
            b1v = (br1 >= 0) ? *(const float4*)&B[(size_t)br1 * ldb + kn] : z4;
        }
#pragma unroll
        for (int ks = 0; ks < 16; ks += 8) {
            unsigned af[4][4], bf[4][2];
#pragma unroll
            for (int i = 0; i < 4; i++) {
                int r = wm + i * 16 + g;
                af[i][0] = As[ks + q][r];     af[i][1] = As[ks + q][r + 8];
                af[i][2] = As[ks + q + 4][r]; af[i][3] = As[ks + q + 4][r + 8];
            }
#pragma unroll
            for (int j = 0; j < 4; j++) {
                int c = wn + j * 8 + g;
                bf[j][0] = Bs[ks + q][c]; bf[j][1] = Bs[ks + q + 4][c];
            }
#pragma unroll
            for (int i = 0; i < 4; i++)
#pragma unroll
                for (int j = 0; j < 4; j++)
                    mma_tf32(acc[i][j][0], acc[i][j][1], acc[i][j][2], acc[i][j][3],
                             af[i][0], af[i][1], af[i][2], af[i][3], bf[j][0], bf[j][1]);
        }
        if (more) {
            __syncthreads();
            As[kq + 0][row0] = f2tf32(a0v.x); As[kq + 1][row0] = f2tf32(a0v.y);
            As[kq + 2][row0] = f2tf32(a0v.z); As[kq + 3][row0] = f2tf32(a0v.w);
            As[kq + 0][row1] = f2tf32(a1v.x); As[kq + 1][row1] = f2tf32(a1v.y);
            As[kq + 2][row1] = f2tf32(a1v.z); As[kq + 3][row1] = f2tf32(a1v.w);
            Bs[kq + 0][row0] = f2tf32(b0v.x); Bs[kq + 1][row0] = f2tf32(b0v.y);
            Bs[kq + 2][row0] = f2tf32(b0v.z); Bs[kq + 3][row0] = f2tf32(b0v.w);
            Bs[kq + 0][row1] = f2tf32(b1v.x); Bs[kq + 1][row1] = f2tf32(b1v.y);
            Bs[kq + 2][row1] = f2tf32(b1v.z); Bs[kq + 3][row1] = f2tf32(b1v.w);
            __syncthreads();
        }
    }

#pragma unroll
    for (int i = 0; i < 4; i++) {
        int r0 = bm + wm + i * 16 + g;
#pragma unroll
        for (int j = 0; j < 4; j++) {
            int c0 = bn + wn + j * 8 + 2 * q;
            if (r0 < M) {
                if (c0 < N)     C[(size_t)r0 * ldc + c0]     = acc[i][j][0];
                if (c0 + 1 < N) C[(size_t)r0 * ldc + c0 + 1] = acc[i][j][1];
            }
            if (r0 + 8 < M) {
                if (c0 < N)     C[(size_t)(r0 + 8) * ldc + c0]     = acc[i][j][2];
                if (c0 + 1 < N) C[(size_t)(r0 + 8) * ldc + c0 + 1] = acc[i][j][3];
            }
        }
    }
}

__global__ __launch_bounds__(256) void k_gemm32(
    const float* __restrict__ A, const float* __restrict__ B, float* __restrict__ C,
    int M, int N, int K) {
    gemm_tf32_body(A, B, C, M, N, blockIdx.y * 128, blockIdx.x * 128, 0, K,
                   nullptr, K, K, (size_t)N);
}

__global__ __launch_bounds__(256) void k_gemm32_splitk(
    const float* __restrict__ A, const float* __restrict__ B, float* __restrict__ Cpart,
    int M, int N, int K, int ks) {
    int z = blockIdx.z;
    int kc = K / ks;
    gemm_tf32_body(A, B, Cpart + (size_t)z * M * N, M, N,
                   blockIdx.y * 128, blockIdx.x * 128, z * kc, z * kc + kc,
                   nullptr, K, K, (size_t)N);
}

__global__ void k_xdb_reduce() {
    int idx = blockIdx.x * 256 + threadIdx.x;
    if (idx >= LSEQ * XPN) return;
    float s = 0.0f;
#pragma unroll
    for (int z = 0; z < XKS; z++) s += g_xdb_part[(size_t)z * LSEQ * XPN + idx];
    g_xdb[idx] = s;
}

// ---------------- causal depthwise conv (K=4) + bias + silu ----------------
__global__ void k_conv(const float* __restrict__ cw, const float* __restrict__ cb) {
    int idx = blockIdx.x * 256 + threadIdx.x;
    if (idx >= LSEQ * DI) return;
    int c = idx % DI, l = idx / DI;
    float s = cb[c];
#pragma unroll
    for (int k = 0; k < 4; k++) {
        int ll = l - 3 + k;
        if (ll >= 0) s += g_xz[(size_t)ll * 2 * DI + c] * cw[c * 4 + k];
    }
    g_xc[idx] = siluf(s);
}

// ---------------- rmsnorm of dt / B / C slices of xdb ----------------
__global__ void k_norm3(const float* __restrict__ wdt, const float* __restrict__ wb,
                        const float* __restrict__ wc) {
    int row = blockIdx.x, i = threadIdx.x;   // 128 threads
    __shared__ float sdt[128];
    __shared__ float sb[16], sc[16];
    float v = g_xdb[row * XPN + i];
    sdt[i] = v * v;
    float bv = 0.f, cv = 0.f;
    if (i < 16) {
        bv = g_xdb[row * XPN + 128 + i];
        cv = g_xdb[row * XPN + 144 + i];
        sb[i] = bv * bv; sc[i] = cv * cv;
    }
    __syncthreads();
    for (int st = 64; st > 0; st >>= 1) { if (i < st) sdt[i] += sdt[i + st]; __syncthreads(); }
    for (int st = 8; st > 0; st >>= 1) { if (i < st) { sb[i] += sb[i + st]; sc[i] += sc[i + st]; } __syncthreads(); }
    float invdt = rsqrtf(sdt[0] / (float)RLOW + EPSF);
    g_dtn[row * RLOW + i] = v * invdt * wdt[i];
    if (i < 16) {
        g_Bn[row * NSTATE + i] = bv * rsqrtf(sb[0] / (float)NSTATE + EPSF) * wb[i];
        g_Cn[row * NSTATE + i] = cv * rsqrtf(sc[0] / (float)NSTATE + EPSF) * wc[i];
    }
}

// ---------------- dt bias + softplus (in place) ----------------
__global__ void k_dtact(const float* __restrict__ b) {
    int idx = blockIdx.x * 256 + threadIdx.x;
    if (idx >= LSEQ * DI) return;
    int c = idx % DI;
    g_dt[idx] = softplusf(g_dt[idx] + b[c]);
}

// ---------------- selective scan: one lane per (d, n), shfl-reduce over n ----
__global__ __launch_bounds__(256) void k_scan(const float* __restrict__ A_log,
                                              const float* __restrict__ Dp) {
    int tid = blockIdx.x * 256 + threadIdx.x;
    int lane = tid & 31;
    int warp = tid >> 5;
    int n = lane & 15;
    int d = warp * 2 + (lane >> 4);
    if (d >= DI) return;
    float Acoef = -expf(A_log[d * NSTATE + n]);
    float Dcoef = Dp[d];
    float h = 0.0f;
    for (int l = 0; l < LSEQ; l++) {
        float dtv = g_dt[(size_t)l * DI + d];
        float xv  = g_xc[(size_t)l * DI + d];
        float bvv = g_Bn[l * NSTATE + n];
        float cvv = g_Cn[l * NSTATE + n];
        float dA = expf(dtv * Acoef);
        h = h * dA + dtv * xv * bvv;
        float y = h * cvv;
        y += __shfl_xor_sync(0xffffffffu, y, 8);
        y += __shfl_xor_sync(0xffffffffu, y, 4);
        y += __shfl_xor_sync(0xffffffffu, y, 2);
        y += __shfl_xor_sync(0xffffffffu, y, 1);
        if (n == 0) {
            float zv = g_xz[(size_t)l * 2 * DI + DI + d];
            g_y[(size_t)l * DI + d] = (y + xv * Dcoef) * siluf(zv);
        }
    }
}

// ---------------- residual add + rmsnorm ----------------
__global__ void k_addrms(const float* __restrict__ hid, const float* __restrict__ w,
                         float* __restrict__ resid_out) {
    int row = blockIdx.x, t = threadIdx.x;
    __shared__ float red[256];
    float s = 0.0f;
    for (int i = t; i < DMODEL; i += 256) {
        float r = g_mamba[row * DMODEL + i] + hid[row * DMODEL + i];
        resid_out[row * DMODEL + i] = r;
        s += r * r;
    }
    red[t] = s; __syncthreads();
    for (int st = 128; st > 0; st >>= 1) { if (t < st) red[t] += red[t + st]; __syncthreads(); }
    float inv = rsqrtf(red[0] / (float)DMODEL + EPSF);
    for (int i = t; i < DMODEL; i += 256)
        g_hs2[row * DMODEL + i] = resid_out[row * DMODEL + i] * inv * w[i];
}

// ---------------- router: logits, softmax, top2, counts ----------------
__global__ void k_zero_router() {
    int t = threadIdx.x;
    if (t < NEXP) { g_cnt[t] = 0; g_cur[t] = 0; }
}

__global__ void k_router(const float* __restrict__ rw) {
    int trow = blockIdx.x, t = threadIdx.x;
    int w = t >> 5, lane = t & 31;
    __shared__ float lg[NEXP];
    float s = 0.0f;
    for (int i = lane; i < DMODEL; i += 32) s += g_hs2[trow * DMODEL + i] * rw[w * DMODEL + i];
    for (int o = 16; o > 0; o >>= 1) s += __shfl_xor_sync(0xffffffffu, s, o);
    if (lane == 0) lg[w] = s;
    __syncthreads();
    if (t == 0) {
        float mx = lg[0];
        for (int e = 1; e < NEXP; e++) mx = fmaxf(mx, lg[e]);
        float ex[NEXP], sum = 0.0f;
        for (int e = 0; e < NEXP; e++) { ex[e] = expf(lg[e] - mx); sum += ex[e]; }
        int e0 = 0;
        for (int e = 1; e < NEXP; e++) if (ex[e] > ex[e0]) e0 = e;
        int e1 = -1;
        for (int e = 0; e < NEXP; e++) if (e != e0 && (e1 < 0 || ex[e] > ex[e1])) e1 = e;
        g_tok_e[2 * trow] = e0; g_tok_e[2 * trow + 1] = e1;
        g_tok_w[2 * trow] = ex[e0] / sum; g_tok_w[2 * trow + 1] = ex[e1] / sum;
        atomicAdd(&g_cnt[e0], 1); atomicAdd(&g_cnt[e1], 1);
    }
}

__global__ void k_offsets() {
    int o = 0;
    for (int e = 0; e < NEXP; e++) { g_off[e] = o; o += g_cnt[e]; }
}

__global__ void k_assign() {
    int t = blockIdx.x * 256 + threadIdx.x;
    if (t >= LSEQ) return;
    for (int j = 0; j < 2; j++) {
        int e = g_tok_e[2 * t + j];
        int p = atomicAdd(&g_cur[e], 1);
        int slot = g_off[e] + p;
        g_assign_tok[slot] = t;
        g_gate[slot] = g_tok_w[2 * t + j];
        g_tok_slot[2 * t + j] = slot;
    }
}

// ---------------- MoE up-projection (gathered rows) ----------------
__global__ __launch_bounds__(256) void k_moe_up32(const float* __restrict__ W,
                                                  float* __restrict__ Obuf) {
    int e = blockIdx.z;
    int cnt = g_cnt[e], off = g_off[e];
    int bm = blockIdx.y * 128;
    if (bm >= cnt) return;
    __shared__ int toks[128];
    int t = threadIdx.x;
    if (t < 128) toks[t] = (bm + t < cnt) ? g_assign_tok[off + bm + t] : -1;
    __syncthreads();
    gemm_tf32_body(g_hs2, W + (size_t)e * ISZ * DMODEL, Obuf + (size_t)off * ISZ,
                   cnt, ISZ, bm, blockIdx.x * 128, 0, DMODEL,
                   toks, DMODEL, DMODEL, (size_t)ISZ);
}

// ---------------- h = silu(g) * u (in place into gbuf) ----------------
__global__ void k_moe_h() {
    int idx = blockIdx.x * 256 + threadIdx.x;
    if (idx >= 2 * LSEQ * ISZ) return;
    float g = g_gbuf[idx];
    g_gbuf[idx] = siluf(g) * g_ubuf[idx];
}

// ---------------- MoE down-projection ----------------
__global__ __launch_bounds__(256) void k_moe_down32(const float* __restrict__ W2) {
    int e = blockIdx.z;
    int cnt = g_cnt[e], off = g_off[e];
    int bm = blockIdx.y * 128;
    if (bm >= cnt) return;
    gemm_tf32_body(g_gbuf + (size_t)off * ISZ, W2 + (size_t)e * DMODEL * ISZ,
                   g_ybuf + (size_t)off * DMODEL,
                   cnt, DMODEL, bm, blockIdx.x * 128, 0, ISZ,
                   nullptr, ISZ, ISZ, (size_t)DMODEL);
}

// ---------------- combine two experts per token ----------------
__global__ void k_combine(float* __restrict__ moe_out) {
    int idx = blockIdx.x * 256 + threadIdx.x;
    if (idx >= LSEQ * DMODEL) return;
    int t = idx / DMODEL, d = idx % DMODEL;
    int s0 = g_tok_slot[2 * t], s1 = g_tok_slot[2 * t + 1];
    moe_out[idx] = g_gate[s0] * g_ybuf[(size_t)s0 * DMODEL + d] +
                   g_gate[s1] * g_ybuf[(size_t)s1 * DMODEL + d];
}

// =======================================================================

extern "C" void kernel_launch(void* const* d_in, const int* in_sizes, int n_in,
                              void* d_out, int out_size) {
    (void)in_sizes; (void)n_in;
    const float* hidden    = (const float*)d_in[0];
    const float* ln_in_w   = (const float*)d_in[1];
    const float* in_proj_w = (const float*)d_in[2];
    const float* conv_w    = (const float*)d_in[3];
    const float* conv_b    = (const float*)d_in[4];
    const float* x_proj_w  = (const float*)d_in[5];
    const float* dt_ln_w   = (const float*)d_in[6];
    const float* b_ln_w    = (const float*)d_in[7];
    const float* c_ln_w    = (const float*)d_in[8];
    const float* dt_proj_w = (const float*)d_in[9];
    const float* dt_proj_b = (const float*)d_in[10];
    const float* A_log     = (const float*)d_in[11];
    const float* D_param   = (const float*)d_in[12];
    const float* out_proj_w= (const float*)d_in[13];
    const float* ln_ff_w   = (const float*)d_in[14];
    const float* router_w  = (const float*)d_in[15];
    const float* w1        = (const float*)d_in[16];
    const float* w3        = (const float*)d_in[17];
    const float* w2        = (const float*)d_in[18];
    float* out = (float*)d_out;
    float* moe_out   = out;                          // [1024,2048]
    float* resid_out = out + (size_t)LSEQ * DMODEL;  // [1024,2048]
    (void)out_size;

    float *p_hsn, *p_xz, *p_xc, *p_xdbp, *p_dtn, *p_dt, *p_y, *p_mamba;
    cudaGetSymbolAddress((void**)&p_hsn, g_hsn);
    cudaGetSymbolAddress((void**)&p_xz, g_xz);
    cudaGetSymbolAddress((void**)&p_xc, g_xc);
    cudaGetSymbolAddress((void**)&p_xdbp, g_xdb_part);
    cudaGetSymbolAddress((void**)&p_dtn, g_dtn);
    cudaGetSymbolAddress((void**)&p_dt, g_dt);
    cudaGetSymbolAddress((void**)&p_y, g_y);
    cudaGetSymbolAddress((void**)&p_mamba, g_mamba);

    // 1. rmsnorm(hidden)
    k_rms1<<<LSEQ, 256>>>(hidden, ln_in_w, p_hsn);
    // 2. in_proj: [1024,8192] = hsn @ in_proj_w^T
    k_gemm32<<<dim3(8192 / 128, LSEQ / 128), 256>>>(p_hsn, in_proj_w, p_xz, LSEQ, 2 * DI, DMODEL);
    // 3. causal conv + silu
    k_conv<<<(LSEQ * DI) / 256, 256>>>(conv_w, conv_b);
    // 4. x_proj (split-K=8): [1024,160] = xc @ x_proj_w^T
    k_gemm32_splitk<<<dim3(2, LSEQ / 128, XKS), 256>>>(p_xc, x_proj_w, p_xdbp, LSEQ, XPN, DI, XKS);
    k_xdb_reduce<<<(LSEQ * XPN + 255) / 256, 256>>>();
    // 5. rmsnorms of dt/B/C
    k_norm3<<<LSEQ, 128>>>(dt_ln_w, b_ln_w, c_ln_w);
    // 6. dt_proj + bias + softplus
    k_gemm32<<<dim3(DI / 128, LSEQ / 128), 256>>>(p_dtn, dt_proj_w, p_dt, LSEQ, DI, RLOW);
    k_dtact<<<(LSEQ * DI) / 256, 256>>>(dt_proj_b);
    // 7. selective scan (+ D skip + silu(z) gate)
    k_scan<<<(DI * NSTATE) / 256, 256>>>(A_log, D_param);
    // 8. out_proj
    k_gemm32<<<dim3(DMODEL / 128, LSEQ / 128), 256>>>(p_y, out_proj_w, p_mamba, LSEQ, DMODEL, DI);
    // 9. residual add + rmsnorm  (residual written straight to d_out)
    k_addrms<<<LSEQ, 256>>>(hidden, ln_ff_w, resid_out);
    // 10. router + expert grouping
    k_zero_router<<<1, 32>>>();
    k_router<<<LSEQ, 256>>>(router_w);
    k_offsets<<<1, 1>>>();
    k_assign<<<LSEQ / 256, 256>>>();
    // 11. MoE up (w1 -> gbuf, w3 -> ubuf)
    float *p_gbuf, *p_ubuf;
    cudaGetSymbolAddress((void**)&p_gbuf, g_gbuf);
    cudaGetSymbolAddress((void**)&p_ubuf, g_ubuf);
    {
        dim3 gup(ISZ / 128, (2 * LSEQ) / 128, NEXP);   // 44 x 16 x 8
        k_moe_up32<<<gup, 256>>>(w1, p_gbuf);
        k_moe_up32<<<gup, 256>>>(w3, p_ubuf);
    }
    // 12. h = silu(g)*u
    k_moe_h<<<(2 * LSEQ * ISZ) / 256, 256>>>();
    // 13. MoE down
    k_moe_down32<<<dim3(DMODEL / 128, (2 * LSEQ) / 128, NEXP), 256>>>(w2);
    // 14. combine with gates -> moe_out
    k_combine<<<(LSEQ * DMODEL) / 256, 256>>>(moe_out);
}